// round 5
// baseline (speedup 1.0000x reference)
#include <cuda_runtime.h>
#include <cuda_bf16.h>
#include <mma.h>

using namespace nvcuda;

#define BB 128
#define TT 256
#define DD 256
#define UU 1024
#define NN 2048
#define BT 32768   // BB*TT
#define NCTA 128   // persistent grid: 16 n-tiles x 8 k-slices

// ---------------- device scratch (static, no runtime alloc) ----------------
__device__ float g_P[(size_t)BT * NN];                       // 256 MB  X@Wx
__device__ __nv_bfloat16 g_Xhi[(size_t)BT * DD];             // 16 MB
__device__ __nv_bfloat16 g_Xlo[(size_t)BT * DD];
__device__ __nv_bfloat16 g_Wxhi[DD * NN];
__device__ __nv_bfloat16 g_Wxlo[DD * NN];
__device__ __nv_bfloat16 g_Whhi[UU * NN];
__device__ __nv_bfloat16 g_Whlo[UU * NN];
__device__ float g_tau[UU];
__device__ float g_h[BB * UU];
__device__ __nv_bfloat16 g_hhi[BB * UU];
__device__ __nv_bfloat16 g_hlo[BB * UU];
__device__ float g_part[8][BB][NN];                          // 8 MB partial sums
__device__ unsigned g_cnt;
__device__ unsigned g_gen;

// ---------------- helpers ----------------
__global__ void split_kernel(const float* __restrict__ src,
                             __nv_bfloat16* __restrict__ hi,
                             __nv_bfloat16* __restrict__ lo, int n) {
    int i = blockIdx.x * blockDim.x + threadIdx.x;
    if (i < n) {
        float v = src[i];
        __nv_bfloat16 h = __float2bfloat16(v);
        hi[i] = h;
        lo[i] = __float2bfloat16(v - __bfloat162float(h));
    }
}

__global__ void init_kernel(const float* __restrict__ w_tau,
                            const float* __restrict__ h0) {
    int i = blockIdx.x * blockDim.x + threadIdx.x;
    if (i < UU) {
        float w = w_tau[i];
        g_tau[i] = log1pf(expf(w));   // softplus
    }
    if (i < BB * UU) {
        float v = h0[i];
        g_h[i] = v;
        __nv_bfloat16 h = __float2bfloat16(v);
        g_hhi[i] = h;
        g_hlo[i] = __float2bfloat16(v - __bfloat162float(h));
    }
    if (i == 0) { g_cnt = 0u; g_gen = 0u; }
}

// ---------------- precompute GEMM: P = X @ Wx (3x bf16 split) ----------------
// grid (256, 32): CTA tile 128(M) x 64(N), K=256. 8 warps = 4(M) x 2(N).
__global__ void __launch_bounds__(256) gemm_x_kernel() {
    int mt = blockIdx.x;          // 0..255
    int nt = blockIdx.y;          // 0..31
    int warp = threadIdx.x >> 5;
    int wm = warp >> 1;           // 0..3
    int wn = warp & 1;            // 0..1
    int row0 = mt * 128 + wm * 32;
    int col0 = nt * 64 + wn * 32;

    wmma::fragment<wmma::accumulator, 16, 16, 16, float> acc[2][2];
#pragma unroll
    for (int i = 0; i < 2; i++)
#pragma unroll
        for (int j = 0; j < 2; j++) wmma::fill_fragment(acc[i][j], 0.0f);

    for (int kc = 0; kc < 16; kc++) {
        wmma::fragment<wmma::matrix_a, 16, 16, 16, __nv_bfloat16, wmma::row_major> ahi[2], alo[2];
        wmma::fragment<wmma::matrix_b, 16, 16, 16, __nv_bfloat16, wmma::row_major> bhi[2], blo[2];
#pragma unroll
        for (int i = 0; i < 2; i++) {
            const __nv_bfloat16* pa = g_Xhi + (size_t)(row0 + 16 * i) * DD + kc * 16;
            const __nv_bfloat16* pl = g_Xlo + (size_t)(row0 + 16 * i) * DD + kc * 16;
            wmma::load_matrix_sync(ahi[i], pa, DD);
            wmma::load_matrix_sync(alo[i], pl, DD);
        }
#pragma unroll
        for (int j = 0; j < 2; j++) {
            const __nv_bfloat16* pb = g_Wxhi + (size_t)(kc * 16) * NN + col0 + 16 * j;
            const __nv_bfloat16* pl = g_Wxlo + (size_t)(kc * 16) * NN + col0 + 16 * j;
            wmma::load_matrix_sync(bhi[j], pb, NN);
            wmma::load_matrix_sync(blo[j], pl, NN);
        }
#pragma unroll
        for (int i = 0; i < 2; i++)
#pragma unroll
            for (int j = 0; j < 2; j++) {
                wmma::mma_sync(acc[i][j], ahi[i], bhi[j], acc[i][j]);
                wmma::mma_sync(acc[i][j], ahi[i], blo[j], acc[i][j]);
                wmma::mma_sync(acc[i][j], alo[i], bhi[j], acc[i][j]);
            }
    }
#pragma unroll
    for (int i = 0; i < 2; i++)
#pragma unroll
        for (int j = 0; j < 2; j++) {
            float* pd = g_P + (size_t)(row0 + 16 * i) * NN + col0 + 16 * j;
            wmma::store_matrix_sync(pd, acc[i][j], NN, wmma::mem_row_major);
        }
}

// ---------------- grid barrier (all 128 CTAs resident: one wave) ----------------
__device__ __forceinline__ void grid_barrier(unsigned target) {
    __syncthreads();
    if (threadIdx.x == 0) {
        __threadfence();
        unsigned old = atomicAdd(&g_cnt, 1u);
        if (old == (unsigned)(gridDim.x - 1)) {
            g_cnt = 0u;
            __threadfence();
            atomicExch(&g_gen, target);
        } else {
            while (*((volatile unsigned*)&g_gen) < target) __nanosleep(100);
        }
        __threadfence();
    }
    __syncthreads();
}

// ---------------- persistent recurrence kernel ----------------
// CTA c: n-tile = c & 15 (128 output cols), k-slice = c >> 4 (128 K).
// Wh hi/lo tile resident in SMEM for all 256 steps.
__global__ void __launch_bounds__(256) rnn_persist_kernel(
    const float* __restrict__ ts,      // [B,T]
    const float* __restrict__ bias,    // [2U]
    float* __restrict__ out)           // [B,T,U]
{
    extern __shared__ __align__(256) __nv_bfloat16 smem[];
    __nv_bfloat16* sBhi = smem;               // [128][128]
    __nv_bfloat16* sBlo = smem + 128 * 128;   // [128][128]

    const int c = blockIdx.x;
    const int n = c & 15;
    const int ks = c >> 4;
    const int tid = threadIdx.x;
    const int warp = tid >> 5;

    // load resident Wh tiles (hi/lo), 16B vectorized
    for (int i = tid; i < 128 * 16; i += 256) {
        int row = i >> 4, q = i & 15;
        const uint4* srch = (const uint4*)(g_Whhi + (size_t)(ks * 128 + row) * NN + n * 128);
        const uint4* srcl = (const uint4*)(g_Whlo + (size_t)(ks * 128 + row) * NN + n * 128);
        ((uint4*)(sBhi + row * 128))[q] = srch[q];
        ((uint4*)(sBlo + row * 128))[q] = srcl[q];
    }
    __syncthreads();

    const int mrow = warp * 16;   // this warp's batch-row block
    unsigned epoch = 0;

    wmma::fragment<wmma::accumulator, 16, 16, 16, float> acc[8];

    for (int t = 0; t < TT; t++) {
        // ---- phase 1: partial GEMM h @ Wh over this K-slice ----
#pragma unroll
        for (int nf = 0; nf < 8; nf++) wmma::fill_fragment(acc[nf], 0.0f);

        for (int kc = 0; kc < 8; kc++) {
            wmma::fragment<wmma::matrix_a, 16, 16, 16, __nv_bfloat16, wmma::row_major> ahi, alo;
            const __nv_bfloat16* pa = g_hhi + (size_t)mrow * UU + ks * 128 + kc * 16;
            const __nv_bfloat16* pl = g_hlo + (size_t)mrow * UU + ks * 128 + kc * 16;
            wmma::load_matrix_sync(ahi, pa, UU);
            wmma::load_matrix_sync(alo, pl, UU);
#pragma unroll
            for (int nf = 0; nf < 8; nf++) {
                wmma::fragment<wmma::matrix_b, 16, 16, 16, __nv_bfloat16, wmma::row_major> bhi, blo;
                wmma::load_matrix_sync(bhi, sBhi + (kc * 16) * 128 + nf * 16, 128);
                wmma::load_matrix_sync(blo, sBlo + (kc * 16) * 128 + nf * 16, 128);
                wmma::mma_sync(acc[nf], ahi, bhi, acc[nf]);
                wmma::mma_sync(acc[nf], ahi, blo, acc[nf]);
                wmma::mma_sync(acc[nf], alo, bhi, acc[nf]);
            }
        }
#pragma unroll
        for (int nf = 0; nf < 8; nf++) {
            float* pd = &g_part[ks][mrow][n * 128 + nf * 16];
            wmma::store_matrix_sync(pd, acc[nf], NN, wmma::mem_row_major);
        }

        grid_barrier(++epoch);

        // ---- phase 2: reduce + LTC cell update; CTA c handles batch row b=c ----
        {
            const int b = c;
            const int r = b * TT + t;
            const float dt = ts[r];
            for (int u = tid; u < UU; u += 256) {
                float sf = 0.f, sa = 0.f;
#pragma unroll
                for (int k2 = 0; k2 < 8; k2++) {
                    sf += g_part[k2][b][u];
                    sa += g_part[k2][b][UU + u];
                }
                float pf = sf + g_P[(size_t)r * NN + u] + bias[u];
                float pa = sa + g_P[(size_t)r * NN + UU + u] + bias[UU + u];
                float f = 1.f / (1.f + expf(-pf));
                float a = tanhf(pa);
                float dec = expf(-dt * (g_tau[u] + f));
                float ho = g_h[b * UU + u];
                float hn = (ho - a) * dec + a;
                g_h[b * UU + u] = hn;
                out[(size_t)b * TT * UU + (size_t)t * UU + u] = hn;
                __nv_bfloat16 hhi = __float2bfloat16(hn);
                g_hhi[b * UU + u] = hhi;
                g_hlo[b * UU + u] = __float2bfloat16(hn - __bfloat162float(hhi));
            }
        }

        grid_barrier(++epoch);
    }
}

// ---------------- launch ----------------
extern "C" void kernel_launch(void* const* d_in, const int* in_sizes, int n_in,
                              void* d_out, int out_size) {
    const float* features   = (const float*)d_in[0];   // [B,T,D]
    const float* time_steps = (const float*)d_in[1];   // [B,T]
    const float* Wx         = (const float*)d_in[2];   // [D,2U]
    const float* Wh         = (const float*)d_in[3];   // [U,2U]
    const float* bias       = (const float*)d_in[4];   // [2U]
    const float* w_tau      = (const float*)d_in[5];   // [U]
    const float* h0         = (const float*)d_in[6];   // [B,U]
    float* out = (float*)d_out;

    // symbol addresses (host API, not a stream op; capture-safe)
    void *pXhi, *pXlo, *pWxhi, *pWxlo, *pWhhi, *pWhlo;
    cudaGetSymbolAddress(&pXhi, g_Xhi);
    cudaGetSymbolAddress(&pXlo, g_Xlo);
    cudaGetSymbolAddress(&pWxhi, g_Wxhi);
    cudaGetSymbolAddress(&pWxlo, g_Wxlo);
    cudaGetSymbolAddress(&pWhhi, g_Whhi);
    cudaGetSymbolAddress(&pWhlo, g_Whlo);

    cudaFuncSetAttribute(rnn_persist_kernel,
                         cudaFuncAttributeMaxDynamicSharedMemorySize, 128 * 128 * 2 * 2);

    // 1) split inputs into bf16 hi/lo
    {
        int n = BT * DD;
        split_kernel<<<(n + 255) / 256, 256>>>(features, (__nv_bfloat16*)pXhi,
                                               (__nv_bfloat16*)pXlo, n);
    }
    {
        int n = DD * NN;
        split_kernel<<<(n + 255) / 256, 256>>>(Wx, (__nv_bfloat16*)pWxhi,
                                               (__nv_bfloat16*)pWxlo, n);
    }
    {
        int n = UU * NN;
        split_kernel<<<(n + 255) / 256, 256>>>(Wh, (__nv_bfloat16*)pWhhi,
                                               (__nv_bfloat16*)pWhlo, n);
    }

    // 2) init h, tau, barrier state
    init_kernel<<<(BB * UU + 255) / 256, 256>>>(w_tau, h0);

    // 3) precompute P = X @ Wx
    {
        dim3 grid(BT / 128, NN / 64);
        gemm_x_kernel<<<grid, 256>>>();
    }

    // 4) persistent sequential scan
    rnn_persist_kernel<<<NCTA, 256, 128 * 128 * 2 * 2>>>(time_steps, bias, out);
}

// round 6
// speedup vs baseline: 1.6311x; 1.6311x over previous
#include <cuda_runtime.h>
#include <cuda_bf16.h>
#include <mma.h>

using namespace nvcuda;

#define BB 128
#define TT 256
#define DD 256
#define UU 1024
#define NN 2048
#define BT 32768   // BB*TT
#define NCTA 128   // persistent grid: 16 n-tiles x 8 k-slices
#define SAP 136    // padded row stride (elems) for 128-wide tiles (16B-shift anti-conflict)
#define SXP 72     // padded row stride for 64-wide tiles

// ---------------- device scratch (static, no runtime alloc) ----------------
__device__ float g_P[(size_t)BT * NN];                       // 256 MB  X@Wx
__device__ __nv_bfloat16 g_Xhi[(size_t)BT * DD];
__device__ __nv_bfloat16 g_Xlo[(size_t)BT * DD];
__device__ __nv_bfloat16 g_Wxhi[DD * NN];
__device__ __nv_bfloat16 g_Wxlo[DD * NN];
__device__ __nv_bfloat16 g_Whhi[UU * NN];
__device__ __nv_bfloat16 g_Whlo[UU * NN];
__device__ float g_tau[UU];
__device__ float g_h[BB * UU];
__device__ __nv_bfloat16 g_hhi[BB * UU];
__device__ __nv_bfloat16 g_hlo[BB * UU];
__device__ float g_part[8][BB][NN];                          // 8 MB partial sums
__device__ unsigned g_cnt;
__device__ unsigned g_gen;

// ---------------- helpers ----------------
__global__ void split_kernel(const float* __restrict__ src,
                             __nv_bfloat16* __restrict__ hi,
                             __nv_bfloat16* __restrict__ lo, int n) {
    int i = blockIdx.x * blockDim.x + threadIdx.x;
    if (i < n) {
        float v = src[i];
        __nv_bfloat16 h = __float2bfloat16(v);
        hi[i] = h;
        lo[i] = __float2bfloat16(v - __bfloat162float(h));
    }
}

__global__ void init_kernel(const float* __restrict__ w_tau,
                            const float* __restrict__ h0) {
    int i = blockIdx.x * blockDim.x + threadIdx.x;
    if (i < UU) {
        float w = w_tau[i];
        g_tau[i] = log1pf(expf(w));   // softplus
    }
    if (i < BB * UU) {
        float v = h0[i];
        g_h[i] = v;
        __nv_bfloat16 h = __float2bfloat16(v);
        g_hhi[i] = h;
        g_hlo[i] = __float2bfloat16(v - __bfloat162float(h));
    }
    if (i == 0) { g_cnt = 0u; g_gen = 0u; }
}

// ---------------- precompute GEMM: P = X @ Wx (3x bf16 split, smem-staged) ----
// grid (256, 16): CTA tile 128(M) x 128(N), K=256 in 4 chunks of 64.
// 8 warps = 4(M) x 2(N): warp tile 32x64.
__global__ void __launch_bounds__(256) gemm_x_kernel() {
    extern __shared__ __align__(16) __nv_bfloat16 smem[];
    __nv_bfloat16* sXhi = smem;                       // [128][SXP]
    __nv_bfloat16* sXlo = sXhi + 128 * SXP;           // [128][SXP]
    __nv_bfloat16* sWhi = sXlo + 128 * SXP;           // [64][SAP]
    __nv_bfloat16* sWlo = sWhi + 64 * SAP;            // [64][SAP]

    const int mt = blockIdx.x;   // 0..255
    const int nt = blockIdx.y;   // 0..15
    const int tid = threadIdx.x;
    const int warp = tid >> 5;
    const int wm = warp >> 1;    // 0..3
    const int wn = warp & 1;     // 0..1

    wmma::fragment<wmma::accumulator, 16, 16, 16, float> acc[2][4];
#pragma unroll
    for (int i = 0; i < 2; i++)
#pragma unroll
        for (int j = 0; j < 4; j++) wmma::fill_fragment(acc[i][j], 0.0f);

    for (int ch = 0; ch < 4; ch++) {
        __syncthreads();
        // stage X chunk: rows mt*128 + [0,128), cols ch*64 + [0,64)
        for (int i = tid; i < 1024; i += 256) {
            int row = i >> 3, q = i & 7;
            const uint4* sh = (const uint4*)(g_Xhi + (size_t)(mt * 128 + row) * DD + ch * 64);
            const uint4* sl = (const uint4*)(g_Xlo + (size_t)(mt * 128 + row) * DD + ch * 64);
            ((uint4*)(sXhi + row * SXP))[q] = sh[q];
            ((uint4*)(sXlo + row * SXP))[q] = sl[q];
        }
        // stage W chunk: rows ch*64 + [0,64), cols nt*128 + [0,128)
        for (int i = tid; i < 1024; i += 256) {
            int row = i >> 4, q = i & 15;
            const uint4* sh = (const uint4*)(g_Wxhi + (size_t)(ch * 64 + row) * NN + nt * 128);
            const uint4* sl = (const uint4*)(g_Wxlo + (size_t)(ch * 64 + row) * NN + nt * 128);
            ((uint4*)(sWhi + row * SAP))[q] = sh[q];
            ((uint4*)(sWlo + row * SAP))[q] = sl[q];
        }
        __syncthreads();

        for (int kc = 0; kc < 4; kc++) {
            wmma::fragment<wmma::matrix_a, 16, 16, 16, __nv_bfloat16, wmma::row_major> ahi[2], alo[2];
#pragma unroll
            for (int m = 0; m < 2; m++) {
                const __nv_bfloat16* p = sXhi + (wm * 32 + m * 16) * SXP + kc * 16;
                wmma::load_matrix_sync(ahi[m], p, SXP);
                wmma::load_matrix_sync(alo[m], sXlo + (wm * 32 + m * 16) * SXP + kc * 16, SXP);
            }
#pragma unroll
            for (int n = 0; n < 4; n++) {
                wmma::fragment<wmma::matrix_b, 16, 16, 16, __nv_bfloat16, wmma::row_major> bhi, blo;
                wmma::load_matrix_sync(bhi, sWhi + (kc * 16) * SAP + wn * 64 + n * 16, SAP);
                wmma::load_matrix_sync(blo, sWlo + (kc * 16) * SAP + wn * 64 + n * 16, SAP);
#pragma unroll
                for (int m = 0; m < 2; m++) {
                    wmma::mma_sync(acc[m][n], ahi[m], bhi, acc[m][n]);
                    wmma::mma_sync(acc[m][n], ahi[m], blo, acc[m][n]);
                    wmma::mma_sync(acc[m][n], alo[m], bhi, acc[m][n]);
                }
            }
        }
    }
#pragma unroll
    for (int m = 0; m < 2; m++)
#pragma unroll
        for (int n = 0; n < 4; n++) {
            float* pd = g_P + (size_t)(mt * 128 + wm * 32 + m * 16) * NN + nt * 128 + wn * 64 + n * 16;
            wmma::store_matrix_sync(pd, acc[m][n], NN, wmma::mem_row_major);
        }
}

// ---------------- grid barrier (all 128 CTAs resident: one wave) ----------------
__device__ __forceinline__ void grid_barrier(unsigned target) {
    __syncthreads();
    if (threadIdx.x == 0) {
        __threadfence();
        unsigned old = atomicAdd(&g_cnt, 1u);
        if (old == (unsigned)(gridDim.x - 1)) {
            g_cnt = 0u;
            __threadfence();
            atomicExch(&g_gen, target);
        } else {
            while (*((volatile unsigned*)&g_gen) < target) __nanosleep(64);
        }
        __threadfence();
    }
    __syncthreads();
}

// ---------------- persistent recurrence kernel ----------------
// CTA c: n-tile = c & 15 (128 output cols), k-slice = c >> 4 (128 K).
// Wh tile loaded ONCE into registers (B fragments) for all 256 steps.
// h slice staged through smem each step (LDSM-fed A fragments).
__global__ void __launch_bounds__(256, 1) rnn_persist_kernel(
    const float* __restrict__ ts,      // [B,T]
    const float* __restrict__ bias,    // [2U]
    float* __restrict__ out)           // [B,T,U]
{
    extern __shared__ __align__(16) __nv_bfloat16 smem[];
    __nv_bfloat16* sm0 = smem;               // [128][SAP]  (B-hi staging, then A-hi)
    __nv_bfloat16* sm1 = smem + 128 * SAP;   // [128][SAP]  (B-lo staging, then A-lo)

    const int c = blockIdx.x;
    const int n = c & 15;
    const int ks = c >> 4;
    const int tid = threadIdx.x;
    const int warp = tid >> 5;
    const int wm = warp >> 2;     // 0..1  (64-row half)
    const int wn = warp & 3;      // 0..3  (32-col quarter)

    // ---- one-time: stage Wh tile, load B fragments into registers ----
    for (int i = tid; i < 2048; i += 256) {
        int row = i >> 4, q = i & 15;
        const uint4* sh = (const uint4*)(g_Whhi + (size_t)(ks * 128 + row) * NN + n * 128);
        const uint4* sl = (const uint4*)(g_Whlo + (size_t)(ks * 128 + row) * NN + n * 128);
        ((uint4*)(sm0 + row * SAP))[q] = sh[q];
        ((uint4*)(sm1 + row * SAP))[q] = sl[q];
    }
    __syncthreads();

    wmma::fragment<wmma::matrix_b, 16, 16, 16, __nv_bfloat16, wmma::row_major> Bhi[8][2], Blo[8][2];
#pragma unroll
    for (int kc = 0; kc < 8; kc++)
#pragma unroll
        for (int nf = 0; nf < 2; nf++) {
            wmma::load_matrix_sync(Bhi[kc][nf], sm0 + (kc * 16) * SAP + wn * 32 + nf * 16, SAP);
            wmma::load_matrix_sync(Blo[kc][nf], sm1 + (kc * 16) * SAP + wn * 32 + nf * 16, SAP);
        }
    __syncthreads();   // all warps done reading before smem is reused for h

    unsigned epoch = 0;
    wmma::fragment<wmma::accumulator, 16, 16, 16, float> acc[4][2];

    for (int t = 0; t < TT; t++) {
        // ---- stage h slice: rows = batch 0..127, cols = ks*128 + [0,128) ----
        for (int i = tid; i < 2048; i += 256) {
            int row = i >> 4, q = i & 15;
            ((uint4*)(sm0 + row * SAP))[q] = ((const uint4*)(g_hhi + (size_t)row * UU + ks * 128))[q];
            ((uint4*)(sm1 + row * SAP))[q] = ((const uint4*)(g_hlo + (size_t)row * UU + ks * 128))[q];
        }
        __syncthreads();

        // ---- partial GEMM: h_slice @ Wh_tile, B in registers ----
#pragma unroll
        for (int m = 0; m < 4; m++)
#pragma unroll
            for (int nf = 0; nf < 2; nf++) wmma::fill_fragment(acc[m][nf], 0.0f);

#pragma unroll
        for (int m = 0; m < 4; m++) {
            const int row = wm * 64 + m * 16;
#pragma unroll
            for (int kc = 0; kc < 8; kc++) {
                wmma::fragment<wmma::matrix_a, 16, 16, 16, __nv_bfloat16, wmma::row_major> ahi, alo;
                wmma::load_matrix_sync(ahi, sm0 + row * SAP + kc * 16, SAP);
                wmma::load_matrix_sync(alo, sm1 + row * SAP + kc * 16, SAP);
#pragma unroll
                for (int nf = 0; nf < 2; nf++) {
                    wmma::mma_sync(acc[m][nf], ahi, Bhi[kc][nf], acc[m][nf]);
                    wmma::mma_sync(acc[m][nf], ahi, Blo[kc][nf], acc[m][nf]);
                    wmma::mma_sync(acc[m][nf], alo, Bhi[kc][nf], acc[m][nf]);
                }
            }
        }
#pragma unroll
        for (int m = 0; m < 4; m++)
#pragma unroll
            for (int nf = 0; nf < 2; nf++) {
                float* pd = &g_part[ks][wm * 64 + m * 16][n * 128 + wn * 32 + nf * 16];
                wmma::store_matrix_sync(pd, acc[m][nf], NN, wmma::mem_row_major);
            }

        grid_barrier(++epoch);

        // ---- reduce + LTC cell update; CTA c handles batch row b=c ----
        {
            const int b = c;
            const int r = b * TT + t;
            const float dt = ts[r];
            for (int u = tid; u < UU; u += 256) {
                float sf = 0.f, sa = 0.f;
#pragma unroll
                for (int k2 = 0; k2 < 8; k2++) {
                    sf += g_part[k2][b][u];
                    sa += g_part[k2][b][UU + u];
                }
                float pf = sf + g_P[(size_t)r * NN + u] + bias[u];
                float pa = sa + g_P[(size_t)r * NN + UU + u] + bias[UU + u];
                float f = 1.f / (1.f + expf(-pf));
                float a = tanhf(pa);
                float dec = expf(-dt * (g_tau[u] + f));
                float ho = g_h[b * UU + u];
                float hn = (ho - a) * dec + a;
                g_h[b * UU + u] = hn;
                out[(size_t)b * TT * UU + (size_t)t * UU + u] = hn;
                __nv_bfloat16 hhi = __float2bfloat16(hn);
                g_hhi[b * UU + u] = hhi;
                g_hlo[b * UU + u] = __float2bfloat16(hn - __bfloat162float(hhi));
            }
        }

        grid_barrier(++epoch);
    }
}

// ---------------- launch ----------------
extern "C" void kernel_launch(void* const* d_in, const int* in_sizes, int n_in,
                              void* d_out, int out_size) {
    const float* features   = (const float*)d_in[0];   // [B,T,D]
    const float* time_steps = (const float*)d_in[1];   // [B,T]
    const float* Wx         = (const float*)d_in[2];   // [D,2U]
    const float* Wh         = (const float*)d_in[3];   // [U,2U]
    const float* bias       = (const float*)d_in[4];   // [2U]
    const float* w_tau      = (const float*)d_in[5];   // [U]
    const float* h0         = (const float*)d_in[6];   // [B,U]
    float* out = (float*)d_out;

    void *pXhi, *pXlo, *pWxhi, *pWxlo, *pWhhi, *pWhlo;
    cudaGetSymbolAddress(&pXhi, g_Xhi);
    cudaGetSymbolAddress(&pXlo, g_Xlo);
    cudaGetSymbolAddress(&pWxhi, g_Wxhi);
    cudaGetSymbolAddress(&pWxlo, g_Wxlo);
    cudaGetSymbolAddress(&pWhhi, g_Whhi);
    cudaGetSymbolAddress(&pWhlo, g_Whlo);

    const int smem_gemm = (2 * 128 * SXP + 2 * 64 * SAP) * 2;   // 71,680 B
    const int smem_rnn  = 2 * 128 * SAP * 2;                    // 69,632 B
    cudaFuncSetAttribute(gemm_x_kernel,
                         cudaFuncAttributeMaxDynamicSharedMemorySize, smem_gemm);
    cudaFuncSetAttribute(rnn_persist_kernel,
                         cudaFuncAttributeMaxDynamicSharedMemorySize, smem_rnn);

    // 1) split inputs into bf16 hi/lo
    {
        int nsz = BT * DD;
        split_kernel<<<(nsz + 255) / 256, 256>>>(features, (__nv_bfloat16*)pXhi,
                                                 (__nv_bfloat16*)pXlo, nsz);
    }
    {
        int nsz = DD * NN;
        split_kernel<<<(nsz + 255) / 256, 256>>>(Wx, (__nv_bfloat16*)pWxhi,
                                                 (__nv_bfloat16*)pWxlo, nsz);
    }
    {
        int nsz = UU * NN;
        split_kernel<<<(nsz + 255) / 256, 256>>>(Wh, (__nv_bfloat16*)pWhhi,
                                                 (__nv_bfloat16*)pWhlo, nsz);
    }

    // 2) init h, tau, barrier state
    init_kernel<<<(BB * UU + 255) / 256, 256>>>(w_tau, h0);

    // 3) precompute P = X @ Wx
    {
        dim3 grid(BT / 128, NN / 128);
        gemm_x_kernel<<<grid, 256, smem_gemm>>>();
    }

    // 4) persistent sequential scan
    rnn_persist_kernel<<<NCTA, 256, smem_rnn>>>(time_steps, bias, out);
}

// round 7
// speedup vs baseline: 2.5783x; 1.5807x over previous
#include <cuda_runtime.h>
#include <cuda_bf16.h>
#include <mma.h>

using namespace nvcuda;

#define BB 128
#define TT 256
#define DD 256
#define UU 1024
#define NN 2048
#define BT 32768   // BB*TT
#define NCTA 128   // persistent grid: 16 n-tiles x 8 k-slices
#define SAP 136    // padded row stride (elems) for 128-wide tiles
#define SXP 72     // padded row stride for 64-wide tiles

// ---------------- device scratch (static, no runtime alloc) ----------------
__device__ float g_P[(size_t)BT * NN];                       // 256 MB  X@Wx
__device__ __nv_bfloat16 g_Xhi[(size_t)BT * DD];
__device__ __nv_bfloat16 g_Xlo[(size_t)BT * DD];
__device__ __nv_bfloat16 g_Wxhi[DD * NN];
__device__ __nv_bfloat16 g_Wxlo[DD * NN];
__device__ __nv_bfloat16 g_Whhi[UU * NN];
__device__ __nv_bfloat16 g_Whlo[UU * NN];
__device__ float g_tau[UU];
__device__ float g_h[BB * UU];
__device__ __nv_bfloat16 g_hhi[BB * UU];
__device__ __nv_bfloat16 g_hlo[BB * UU];
__device__ float g_part[8][BB][NN];                          // 8 MB partial sums
__device__ unsigned g_cnt;
__device__ unsigned g_gen;

// ---------------- helpers ----------------
__global__ void split_kernel(const float* __restrict__ src,
                             __nv_bfloat16* __restrict__ hi,
                             __nv_bfloat16* __restrict__ lo, int n) {
    int i = blockIdx.x * blockDim.x + threadIdx.x;
    if (i < n) {
        float v = src[i];
        __nv_bfloat16 h = __float2bfloat16(v);
        hi[i] = h;
        lo[i] = __float2bfloat16(v - __bfloat162float(h));
    }
}

__global__ void init_kernel(const float* __restrict__ w_tau,
                            const float* __restrict__ h0) {
    int i = blockIdx.x * blockDim.x + threadIdx.x;
    if (i < UU) {
        float w = w_tau[i];
        g_tau[i] = log1pf(expf(w));   // softplus
    }
    if (i < BB * UU) {
        float v = h0[i];
        g_h[i] = v;
        __nv_bfloat16 h = __float2bfloat16(v);
        g_hhi[i] = h;
        g_hlo[i] = __float2bfloat16(v - __bfloat162float(h));
    }
    if (i == 0) { g_cnt = 0u; g_gen = 0u; }
}

// ---------------- precompute GEMM: P = X @ Wx (3x bf16 split, smem-staged) ----
// grid (256, 16): CTA tile 128(M) x 128(N), K=256 in 4 chunks of 64.
__global__ void __launch_bounds__(256) gemm_x_kernel() {
    extern __shared__ __align__(16) __nv_bfloat16 smem[];
    __nv_bfloat16* sXhi = smem;                       // [128][SXP]
    __nv_bfloat16* sXlo = sXhi + 128 * SXP;           // [128][SXP]
    __nv_bfloat16* sWhi = sXlo + 128 * SXP;           // [64][SAP]
    __nv_bfloat16* sWlo = sWhi + 64 * SAP;            // [64][SAP]

    const int mt = blockIdx.x;   // 0..255
    const int nt = blockIdx.y;   // 0..15
    const int tid = threadIdx.x;
    const int warp = tid >> 5;
    const int wm = warp >> 1;    // 0..3
    const int wn = warp & 1;     // 0..1

    wmma::fragment<wmma::accumulator, 16, 16, 16, float> acc[2][4];
#pragma unroll
    for (int i = 0; i < 2; i++)
#pragma unroll
        for (int j = 0; j < 4; j++) wmma::fill_fragment(acc[i][j], 0.0f);

    for (int ch = 0; ch < 4; ch++) {
        __syncthreads();
        for (int i = tid; i < 1024; i += 256) {
            int row = i >> 3, q = i & 7;
            const uint4* sh = (const uint4*)(g_Xhi + (size_t)(mt * 128 + row) * DD + ch * 64);
            const uint4* sl = (const uint4*)(g_Xlo + (size_t)(mt * 128 + row) * DD + ch * 64);
            ((uint4*)(sXhi + row * SXP))[q] = sh[q];
            ((uint4*)(sXlo + row * SXP))[q] = sl[q];
        }
        for (int i = tid; i < 1024; i += 256) {
            int row = i >> 4, q = i & 15;
            const uint4* sh = (const uint4*)(g_Wxhi + (size_t)(ch * 64 + row) * NN + nt * 128);
            const uint4* sl = (const uint4*)(g_Wxlo + (size_t)(ch * 64 + row) * NN + nt * 128);
            ((uint4*)(sWhi + row * SAP))[q] = sh[q];
            ((uint4*)(sWlo + row * SAP))[q] = sl[q];
        }
        __syncthreads();

        for (int kc = 0; kc < 4; kc++) {
            wmma::fragment<wmma::matrix_a, 16, 16, 16, __nv_bfloat16, wmma::row_major> ahi[2], alo[2];
#pragma unroll
            for (int m = 0; m < 2; m++) {
                wmma::load_matrix_sync(ahi[m], sXhi + (wm * 32 + m * 16) * SXP + kc * 16, SXP);
                wmma::load_matrix_sync(alo[m], sXlo + (wm * 32 + m * 16) * SXP + kc * 16, SXP);
            }
#pragma unroll
            for (int n = 0; n < 4; n++) {
                wmma::fragment<wmma::matrix_b, 16, 16, 16, __nv_bfloat16, wmma::row_major> bhi, blo;
                wmma::load_matrix_sync(bhi, sWhi + (kc * 16) * SAP + wn * 64 + n * 16, SAP);
                wmma::load_matrix_sync(blo, sWlo + (kc * 16) * SAP + wn * 64 + n * 16, SAP);
#pragma unroll
                for (int m = 0; m < 2; m++) {
                    wmma::mma_sync(acc[m][n], ahi[m], bhi, acc[m][n]);
                    wmma::mma_sync(acc[m][n], ahi[m], blo, acc[m][n]);
                    wmma::mma_sync(acc[m][n], alo[m], bhi, acc[m][n]);
                }
            }
        }
    }
#pragma unroll
    for (int m = 0; m < 2; m++)
#pragma unroll
        for (int n = 0; n < 4; n++) {
            float* pd = g_P + (size_t)(mt * 128 + wm * 32 + m * 16) * NN + nt * 128 + wn * 64 + n * 16;
            wmma::store_matrix_sync(pd, acc[m][n], NN, wmma::mem_row_major);
        }
}

// ---------------- grid barrier (all 128 CTAs resident: one wave) ----------------
__device__ __forceinline__ void grid_barrier(unsigned target) {
    __syncthreads();
    if (threadIdx.x == 0) {
        __threadfence();
        unsigned old = atomicAdd(&g_cnt, 1u);
        if (old == (unsigned)(gridDim.x - 1)) {
            g_cnt = 0u;
            __threadfence();
            atomicExch(&g_gen, target);
        } else {
            while (*((volatile unsigned*)&g_gen) < target) __nanosleep(64);
        }
        __threadfence();
    }
    __syncthreads();
}

// ---------------- persistent recurrence kernel ----------------
// CTA c: n-tile = c & 15 (128 output cols), k-slice = c >> 4 (128 K).
// Warp w owns 16-col strip: cols n*128 + w*16, all 128 M rows.
// Resident B: 16 fragments (64 regs). acc: 8 fragments (64 regs). No spill.
__global__ void __launch_bounds__(256, 1) rnn_persist_kernel(
    const float* __restrict__ ts,      // [B,T]
    const float* __restrict__ bias,    // [2U]
    float* __restrict__ out)           // [B,T,U]
{
    extern __shared__ __align__(16) __nv_bfloat16 smem[];
    __nv_bfloat16* sm0 = smem;               // [128][SAP]
    __nv_bfloat16* sm1 = smem + 128 * SAP;   // [128][SAP]

    const int c = blockIdx.x;
    const int n = c & 15;
    const int ks = c >> 4;
    const int tid = threadIdx.x;
    const int warp = tid >> 5;

    // ---- one-time: stage Wh tile, load resident B fragments ----
    for (int i = tid; i < 2048; i += 256) {
        int row = i >> 4, q = i & 15;
        const uint4* sh = (const uint4*)(g_Whhi + (size_t)(ks * 128 + row) * NN + n * 128);
        const uint4* sl = (const uint4*)(g_Whlo + (size_t)(ks * 128 + row) * NN + n * 128);
        ((uint4*)(sm0 + row * SAP))[q] = sh[q];
        ((uint4*)(sm1 + row * SAP))[q] = sl[q];
    }
    __syncthreads();

    wmma::fragment<wmma::matrix_b, 16, 16, 16, __nv_bfloat16, wmma::row_major> Bhi[8], Blo[8];
#pragma unroll
    for (int kc = 0; kc < 8; kc++) {
        wmma::load_matrix_sync(Bhi[kc], sm0 + (kc * 16) * SAP + warp * 16, SAP);
        wmma::load_matrix_sync(Blo[kc], sm1 + (kc * 16) * SAP + warp * 16, SAP);
    }
    __syncthreads();   // all warps done reading before smem reuse

    unsigned epoch = 0;
    wmma::fragment<wmma::accumulator, 16, 16, 16, float> acc[8];

    for (int t = 0; t < TT; t++) {
        // ---- stage h slice: rows = batch 0..127, cols = ks*128 + [0,128) ----
        for (int i = tid; i < 2048; i += 256) {
            int row = i >> 4, q = i & 15;
            ((uint4*)(sm0 + row * SAP))[q] = ((const uint4*)(g_hhi + (size_t)row * UU + ks * 128))[q];
            ((uint4*)(sm1 + row * SAP))[q] = ((const uint4*)(g_hlo + (size_t)row * UU + ks * 128))[q];
        }
        __syncthreads();

        // ---- partial GEMM: h_slice @ Wh_tile ----
#pragma unroll
        for (int m = 0; m < 8; m++) wmma::fill_fragment(acc[m], 0.0f);

#pragma unroll
        for (int kc = 0; kc < 8; kc++) {
#pragma unroll
            for (int m = 0; m < 8; m++) {
                wmma::fragment<wmma::matrix_a, 16, 16, 16, __nv_bfloat16, wmma::row_major> ahi, alo;
                wmma::load_matrix_sync(ahi, sm0 + (m * 16) * SAP + kc * 16, SAP);
                wmma::load_matrix_sync(alo, sm1 + (m * 16) * SAP + kc * 16, SAP);
                wmma::mma_sync(acc[m], ahi, Bhi[kc], acc[m]);
                wmma::mma_sync(acc[m], ahi, Blo[kc], acc[m]);
                wmma::mma_sync(acc[m], alo, Bhi[kc], acc[m]);
            }
        }
#pragma unroll
        for (int m = 0; m < 8; m++) {
            float* pd = &g_part[ks][m * 16][n * 128 + warp * 16];
            wmma::store_matrix_sync(pd, acc[m], NN, wmma::mem_row_major);
        }

        grid_barrier(++epoch);

        // ---- reduce + LTC cell update; CTA c handles batch row b=c ----
        {
            const int b = c;
            const int r = b * TT + t;
            const float dt = ts[r];
            const int u0 = tid * 4;   // 256 threads x 4 = 1024 cols

            float4 sf = make_float4(0.f, 0.f, 0.f, 0.f);
            float4 sa = make_float4(0.f, 0.f, 0.f, 0.f);
#pragma unroll
            for (int k2 = 0; k2 < 8; k2++) {
                float4 vf = *(const float4*)&g_part[k2][b][u0];
                float4 va = *(const float4*)&g_part[k2][b][UU + u0];
                sf.x += vf.x; sf.y += vf.y; sf.z += vf.z; sf.w += vf.w;
                sa.x += va.x; sa.y += va.y; sa.z += va.z; sa.w += va.w;
            }
            float4 Pf = *(const float4*)&g_P[(size_t)r * NN + u0];
            float4 Pa = *(const float4*)&g_P[(size_t)r * NN + UU + u0];
            float4 bf = *(const float4*)&bias[u0];
            float4 ba = *(const float4*)&bias[UU + u0];
            float4 tu = *(const float4*)&g_tau[u0];
            float4 ho = *(const float4*)&g_h[b * UU + u0];

            float hn[4];
#pragma unroll
            for (int j = 0; j < 4; j++) {
                float pf = ((const float*)&sf)[j] + ((const float*)&Pf)[j] + ((const float*)&bf)[j];
                float pa = ((const float*)&sa)[j] + ((const float*)&Pa)[j] + ((const float*)&ba)[j];
                float f = 1.f / (1.f + expf(-pf));
                float a = tanhf(pa);
                float dec = expf(-dt * (((const float*)&tu)[j] + f));
                hn[j] = (((const float*)&ho)[j] - a) * dec + a;
            }

            *(float4*)&g_h[b * UU + u0] = make_float4(hn[0], hn[1], hn[2], hn[3]);
            *(float4*)&out[(size_t)b * TT * UU + (size_t)t * UU + u0] =
                make_float4(hn[0], hn[1], hn[2], hn[3]);

            __nv_bfloat16 hi[4], lo[4];
#pragma unroll
            for (int j = 0; j < 4; j++) {
                hi[j] = __float2bfloat16(hn[j]);
                lo[j] = __float2bfloat16(hn[j] - __bfloat162float(hi[j]));
            }
            *(uint2*)&g_hhi[b * UU + u0] = *(const uint2*)hi;
            *(uint2*)&g_hlo[b * UU + u0] = *(const uint2*)lo;
        }

        grid_barrier(++epoch);
    }
}

// ---------------- launch ----------------
extern "C" void kernel_launch(void* const* d_in, const int* in_sizes, int n_in,
                              void* d_out, int out_size) {
    const float* features   = (const float*)d_in[0];   // [B,T,D]
    const float* time_steps = (const float*)d_in[1];   // [B,T]
    const float* Wx         = (const float*)d_in[2];   // [D,2U]
    const float* Wh         = (const float*)d_in[3];   // [U,2U]
    const float* bias       = (const float*)d_in[4];   // [2U]
    const float* w_tau      = (const float*)d_in[5];   // [U]
    const float* h0         = (const float*)d_in[6];   // [B,U]
    float* out = (float*)d_out;

    void *pXhi, *pXlo, *pWxhi, *pWxlo, *pWhhi, *pWhlo;
    cudaGetSymbolAddress(&pXhi, g_Xhi);
    cudaGetSymbolAddress(&pXlo, g_Xlo);
    cudaGetSymbolAddress(&pWxhi, g_Wxhi);
    cudaGetSymbolAddress(&pWxlo, g_Wxlo);
    cudaGetSymbolAddress(&pWhhi, g_Whhi);
    cudaGetSymbolAddress(&pWhlo, g_Whlo);

    const int smem_gemm = (2 * 128 * SXP + 2 * 64 * SAP) * 2;   // 71,680 B
    const int smem_rnn  = 2 * 128 * SAP * 2;                    // 69,632 B
    cudaFuncSetAttribute(gemm_x_kernel,
                         cudaFuncAttributeMaxDynamicSharedMemorySize, smem_gemm);
    cudaFuncSetAttribute(rnn_persist_kernel,
                         cudaFuncAttributeMaxDynamicSharedMemorySize, smem_rnn);

    // 1) split inputs into bf16 hi/lo
    {
        int nsz = BT * DD;
        split_kernel<<<(nsz + 255) / 256, 256>>>(features, (__nv_bfloat16*)pXhi,
                                                 (__nv_bfloat16*)pXlo, nsz);
    }
    {
        int nsz = DD * NN;
        split_kernel<<<(nsz + 255) / 256, 256>>>(Wx, (__nv_bfloat16*)pWxhi,
                                                 (__nv_bfloat16*)pWxlo, nsz);
    }
    {
        int nsz = UU * NN;
        split_kernel<<<(nsz + 255) / 256, 256>>>(Wh, (__nv_bfloat16*)pWhhi,
                                                 (__nv_bfloat16*)pWhlo, nsz);
    }

    // 2) init h, tau, barrier state
    init_kernel<<<(BB * UU + 255) / 256, 256>>>(w_tau, h0);

    // 3) precompute P = X @ Wx
    {
        dim3 grid(BT / 128, NN / 128);
        gemm_x_kernel<<<grid, 256, smem_gemm>>>();
    }

    // 4) persistent sequential scan
    rnn_persist_kernel<<<NCTA, 256, smem_rnn>>>(time_steps, bias, out);
}

// round 8
// speedup vs baseline: 2.6982x; 1.0465x over previous
#include <cuda_runtime.h>
#include <cuda_bf16.h>
#include <mma.h>

using namespace nvcuda;

#define BB 128
#define TT 256
#define DD 256
#define UU 1024
#define NN 2048
#define BT 32768   // BB*TT
#define NCTA 128   // persistent grid: 16 n-tiles x 8 k-slices
#define SAP 136    // padded row stride (elems) for 128-wide tiles
#define SXP 72     // padded row stride for 64-wide tiles

// ---------------- device scratch (static, no runtime alloc) ----------------
__device__ float g_P[(size_t)BT * NN];                       // 256 MB  X@Wx
__device__ __nv_bfloat16 g_Xhi[(size_t)BT * DD];
__device__ __nv_bfloat16 g_Xlo[(size_t)BT * DD];
__device__ __nv_bfloat16 g_Wxhi[DD * NN];
__device__ __nv_bfloat16 g_Wxlo[DD * NN];
__device__ __nv_bfloat16 g_Whhi[UU * NN];
__device__ __nv_bfloat16 g_Whlo[UU * NN];
__device__ float g_tau[UU];
__device__ __nv_bfloat16 g_hhi[BB * UU];
__device__ __nv_bfloat16 g_hlo[BB * UU];
__device__ float g_part[8][BB][NN];                          // 8 MB partial sums
__device__ unsigned g_cnt;
__device__ unsigned g_gen;

// ---------------- one merged prep kernel (splits + tau + h init) -----------
__global__ void prep_kernel(const float* __restrict__ features,
                            const float* __restrict__ Wx,
                            const float* __restrict__ Wh,
                            const float* __restrict__ w_tau,
                            const float* __restrict__ h0) {
    const int gid = blockIdx.x * blockDim.x + threadIdx.x;
    const int stride = gridDim.x * blockDim.x;

    for (int i = gid; i < BT * DD; i += stride) {
        float v = features[i];
        __nv_bfloat16 h = __float2bfloat16(v);
        g_Xhi[i] = h;
        g_Xlo[i] = __float2bfloat16(v - __bfloat162float(h));
    }
    for (int i = gid; i < DD * NN; i += stride) {
        float v = Wx[i];
        __nv_bfloat16 h = __float2bfloat16(v);
        g_Wxhi[i] = h;
        g_Wxlo[i] = __float2bfloat16(v - __bfloat162float(h));
    }
    for (int i = gid; i < UU * NN; i += stride) {
        float v = Wh[i];
        __nv_bfloat16 h = __float2bfloat16(v);
        g_Whhi[i] = h;
        g_Whlo[i] = __float2bfloat16(v - __bfloat162float(h));
    }
    for (int i = gid; i < UU; i += stride) {
        float w = w_tau[i];
        g_tau[i] = log1pf(expf(w));   // softplus (prep only: full precision)
    }
    for (int i = gid; i < BB * UU; i += stride) {
        float v = h0[i];
        __nv_bfloat16 h = __float2bfloat16(v);
        g_hhi[i] = h;
        g_hlo[i] = __float2bfloat16(v - __bfloat162float(h));
    }
    if (gid == 0) { g_cnt = 0u; g_gen = 0u; }
}

// ---------------- precompute GEMM: P = X @ Wx (3x bf16 split, smem-staged) ----
// grid (256, 16): CTA tile 128(M) x 128(N), K=256 in 4 chunks of 64.
__global__ void __launch_bounds__(256) gemm_x_kernel() {
    extern __shared__ __align__(16) __nv_bfloat16 smem[];
    __nv_bfloat16* sXhi = smem;                       // [128][SXP]
    __nv_bfloat16* sXlo = sXhi + 128 * SXP;           // [128][SXP]
    __nv_bfloat16* sWhi = sXlo + 128 * SXP;           // [64][SAP]
    __nv_bfloat16* sWlo = sWhi + 64 * SAP;            // [64][SAP]

    const int mt = blockIdx.x;
    const int nt = blockIdx.y;
    const int tid = threadIdx.x;
    const int warp = tid >> 5;
    const int wm = warp >> 1;
    const int wn = warp & 1;

    wmma::fragment<wmma::accumulator, 16, 16, 16, float> acc[2][4];
#pragma unroll
    for (int i = 0; i < 2; i++)
#pragma unroll
        for (int j = 0; j < 4; j++) wmma::fill_fragment(acc[i][j], 0.0f);

    for (int ch = 0; ch < 4; ch++) {
        __syncthreads();
        for (int i = tid; i < 1024; i += 256) {
            int row = i >> 3, q = i & 7;
            const uint4* sh = (const uint4*)(g_Xhi + (size_t)(mt * 128 + row) * DD + ch * 64);
            const uint4* sl = (const uint4*)(g_Xlo + (size_t)(mt * 128 + row) * DD + ch * 64);
            ((uint4*)(sXhi + row * SXP))[q] = sh[q];
            ((uint4*)(sXlo + row * SXP))[q] = sl[q];
        }
        for (int i = tid; i < 1024; i += 256) {
            int row = i >> 4, q = i & 15;
            const uint4* sh = (const uint4*)(g_Wxhi + (size_t)(ch * 64 + row) * NN + nt * 128);
            const uint4* sl = (const uint4*)(g_Wxlo + (size_t)(ch * 64 + row) * NN + nt * 128);
            ((uint4*)(sWhi + row * SAP))[q] = sh[q];
            ((uint4*)(sWlo + row * SAP))[q] = sl[q];
        }
        __syncthreads();

        for (int kc = 0; kc < 4; kc++) {
            wmma::fragment<wmma::matrix_a, 16, 16, 16, __nv_bfloat16, wmma::row_major> ahi[2], alo[2];
#pragma unroll
            for (int m = 0; m < 2; m++) {
                wmma::load_matrix_sync(ahi[m], sXhi + (wm * 32 + m * 16) * SXP + kc * 16, SXP);
                wmma::load_matrix_sync(alo[m], sXlo + (wm * 32 + m * 16) * SXP + kc * 16, SXP);
            }
#pragma unroll
            for (int n = 0; n < 4; n++) {
                wmma::fragment<wmma::matrix_b, 16, 16, 16, __nv_bfloat16, wmma::row_major> bhi, blo;
                wmma::load_matrix_sync(bhi, sWhi + (kc * 16) * SAP + wn * 64 + n * 16, SAP);
                wmma::load_matrix_sync(blo, sWlo + (kc * 16) * SAP + wn * 64 + n * 16, SAP);
#pragma unroll
                for (int m = 0; m < 2; m++) {
                    wmma::mma_sync(acc[m][n], ahi[m], bhi, acc[m][n]);
                    wmma::mma_sync(acc[m][n], ahi[m], blo, acc[m][n]);
                    wmma::mma_sync(acc[m][n], alo[m], bhi, acc[m][n]);
                }
            }
        }
    }
#pragma unroll
    for (int m = 0; m < 2; m++)
#pragma unroll
        for (int n = 0; n < 4; n++) {
            float* pd = g_P + (size_t)(mt * 128 + wm * 32 + m * 16) * NN + nt * 128 + wn * 64 + n * 16;
            wmma::store_matrix_sync(pd, acc[m][n], NN, wmma::mem_row_major);
        }
}

// ---------------- split grid barrier (arrive / wait) ----------------
__device__ __forceinline__ void bar_arrive(unsigned target) {
    __syncthreads();
    if (threadIdx.x == 0) {
        __threadfence();
        if (atomicAdd(&g_cnt, 1u) == (unsigned)(NCTA - 1)) {
            g_cnt = 0u;
            __threadfence();
            atomicExch(&g_gen, target);
        }
    }
}
__device__ __forceinline__ void bar_wait(unsigned target) {
    if (threadIdx.x == 0) {
        while (*((volatile unsigned*)&g_gen) < target) __nanosleep(64);
        __threadfence();
    }
    __syncthreads();
}

// ---------------- persistent recurrence kernel ----------------
// CTA c: n-tile = c & 15 (128 output cols), k-slice = c >> 4 (128 K).
// Warp w owns 16-col strip. Resident B: 16 frags. h row c lives in registers.
__global__ void __launch_bounds__(256, 1) rnn_persist_kernel(
    const float* __restrict__ ts,      // [B,T]
    const float* __restrict__ bias,    // [2U]
    const float* __restrict__ h0,      // [B,U]
    float* __restrict__ out)           // [B,T,U]
{
    extern __shared__ __align__(16) __nv_bfloat16 smem[];
    __nv_bfloat16* sm0 = smem;               // [128][SAP]
    __nv_bfloat16* sm1 = smem + 128 * SAP;   // [128][SAP]
    float* s_ts = (float*)(sm1 + 128 * SAP); // [TT]

    const int c = blockIdx.x;
    const int n = c & 15;
    const int ks = c >> 4;
    const int tid = threadIdx.x;
    const int warp = tid >> 5;
    const int u0 = tid * 4;

    // ---- one-time: stage Wh tile, load resident B fragments, ts row, consts ----
    for (int i = tid; i < 2048; i += 256) {
        int row = i >> 4, q = i & 15;
        const uint4* sh = (const uint4*)(g_Whhi + (size_t)(ks * 128 + row) * NN + n * 128);
        const uint4* sl = (const uint4*)(g_Whlo + (size_t)(ks * 128 + row) * NN + n * 128);
        ((uint4*)(sm0 + row * SAP))[q] = sh[q];
        ((uint4*)(sm1 + row * SAP))[q] = sl[q];
    }
    for (int i = tid; i < TT; i += 256) s_ts[i] = ts[c * TT + i];
    __syncthreads();

    wmma::fragment<wmma::matrix_b, 16, 16, 16, __nv_bfloat16, wmma::row_major> Bhi[8], Blo[8];
#pragma unroll
    for (int kc = 0; kc < 8; kc++) {
        wmma::load_matrix_sync(Bhi[kc], sm0 + (kc * 16) * SAP + warp * 16, SAP);
        wmma::load_matrix_sync(Blo[kc], sm1 + (kc * 16) * SAP + warp * 16, SAP);
    }
    __syncthreads();   // all warps done reading before smem reuse

    // loop-invariant registers
    const float4 bf_c = *(const float4*)&bias[u0];
    const float4 ba_c = *(const float4*)&bias[UU + u0];
    const float4 tu_c = *(const float4*)&g_tau[u0];
    float4 h_reg = *(const float4*)&h0[c * UU + u0];

    wmma::fragment<wmma::accumulator, 16, 16, 16, float> acc[8];

    for (int t = 0; t < TT; t++) {
        // ---- stage h slice: rows = batch 0..127, cols = ks*128 + [0,128) ----
        for (int i = tid; i < 2048; i += 256) {
            int row = i >> 4, q = i & 15;
            ((uint4*)(sm0 + row * SAP))[q] = __ldcg(((const uint4*)(g_hhi + (size_t)row * UU + ks * 128)) + q);
            ((uint4*)(sm1 + row * SAP))[q] = __ldcg(((const uint4*)(g_hlo + (size_t)row * UU + ks * 128)) + q);
        }
        __syncthreads();

        // ---- partial GEMM: h_slice @ Wh_tile ----
#pragma unroll
        for (int m = 0; m < 8; m++) wmma::fill_fragment(acc[m], 0.0f);
#pragma unroll
        for (int kc = 0; kc < 8; kc++) {
#pragma unroll
            for (int m = 0; m < 8; m++) {
                wmma::fragment<wmma::matrix_a, 16, 16, 16, __nv_bfloat16, wmma::row_major> ahi, alo;
                wmma::load_matrix_sync(ahi, sm0 + (m * 16) * SAP + kc * 16, SAP);
                wmma::load_matrix_sync(alo, sm1 + (m * 16) * SAP + kc * 16, SAP);
                wmma::mma_sync(acc[m], ahi, Bhi[kc], acc[m]);
                wmma::mma_sync(acc[m], ahi, Blo[kc], acc[m]);
                wmma::mma_sync(acc[m], alo, Bhi[kc], acc[m]);
            }
        }
#pragma unroll
        for (int m = 0; m < 8; m++) {
            float* pd = &g_part[ks][m * 16][n * 128 + warp * 16];
            wmma::store_matrix_sync(pd, acc[m], NN, wmma::mem_row_major);
        }

        // ---- barrier 1 with P/dt prefetch hidden in the wait ----
        const unsigned e1 = 2u * t + 1u;
        bar_arrive(e1);
        const int r = c * TT + t;
        const float4 Pf = *(const float4*)&g_P[(size_t)r * NN + u0];
        const float4 Pa = *(const float4*)&g_P[(size_t)r * NN + UU + u0];
        const float dt = s_ts[t];
        bar_wait(e1);

        // ---- reduce + LTC cell update; CTA c handles batch row b=c ----
        {
            float4 sf = make_float4(0.f, 0.f, 0.f, 0.f);
            float4 sa = make_float4(0.f, 0.f, 0.f, 0.f);
#pragma unroll
            for (int k2 = 0; k2 < 8; k2++) {
                float4 vf = __ldcg((const float4*)&g_part[k2][c][u0]);
                float4 va = __ldcg((const float4*)&g_part[k2][c][UU + u0]);
                sf.x += vf.x; sf.y += vf.y; sf.z += vf.z; sf.w += vf.w;
                sa.x += va.x; sa.y += va.y; sa.z += va.z; sa.w += va.w;
            }

            float hn[4];
#pragma unroll
            for (int j = 0; j < 4; j++) {
                float pf = ((const float*)&sf)[j] + ((const float*)&Pf)[j] + ((const float*)&bf_c)[j];
                float pa = ((const float*)&sa)[j] + ((const float*)&Pa)[j] + ((const float*)&ba_c)[j];
                float f = __fdividef(1.f, 1.f + __expf(-pf));
                float a = 1.f - __fdividef(2.f, __expf(2.f * pa) + 1.f);   // tanh
                float dec = __expf(-dt * (((const float*)&tu_c)[j] + f));
                float ho = ((const float*)&h_reg)[j];
                hn[j] = (ho - a) * dec + a;
            }
            h_reg = make_float4(hn[0], hn[1], hn[2], hn[3]);

            *(float4*)&out[(size_t)c * TT * UU + (size_t)t * UU + u0] = h_reg;

            __nv_bfloat16 hi[4], lo[4];
#pragma unroll
            for (int j = 0; j < 4; j++) {
                hi[j] = __float2bfloat16(hn[j]);
                lo[j] = __float2bfloat16(hn[j] - __bfloat162float(hi[j]));
            }
            *(uint2*)&g_hhi[c * UU + u0] = *(const uint2*)hi;
            *(uint2*)&g_hlo[c * UU + u0] = *(const uint2*)lo;
        }

        // ---- barrier 2 (h published before next step's staging) ----
        const unsigned e2 = 2u * t + 2u;
        bar_arrive(e2);
        bar_wait(e2);
    }
}

// ---------------- launch ----------------
extern "C" void kernel_launch(void* const* d_in, const int* in_sizes, int n_in,
                              void* d_out, int out_size) {
    const float* features   = (const float*)d_in[0];   // [B,T,D]
    const float* time_steps = (const float*)d_in[1];   // [B,T]
    const float* Wx         = (const float*)d_in[2];   // [D,2U]
    const float* Wh         = (const float*)d_in[3];   // [U,2U]
    const float* bias       = (const float*)d_in[4];   // [2U]
    const float* w_tau      = (const float*)d_in[5];   // [U]
    const float* h0         = (const float*)d_in[6];   // [B,U]
    float* out = (float*)d_out;

    const int smem_gemm = (2 * 128 * SXP + 2 * 64 * SAP) * 2;        // 71,680 B
    const int smem_rnn  = 2 * 128 * SAP * 2 + TT * 4;                // 70,656 B
    cudaFuncSetAttribute(gemm_x_kernel,
                         cudaFuncAttributeMaxDynamicSharedMemorySize, smem_gemm);
    cudaFuncSetAttribute(rnn_persist_kernel,
                         cudaFuncAttributeMaxDynamicSharedMemorySize, smem_rnn);

    // 1) merged prep: splits + tau + h init + barrier reset
    prep_kernel<<<2048, 256>>>(features, Wx, Wh, w_tau, h0);

    // 2) precompute P = X @ Wx
    {
        dim3 grid(BT / 128, NN / 128);
        gemm_x_kernel<<<grid, 256, smem_gemm>>>();
    }

    // 3) persistent sequential scan
    rnn_persist_kernel<<<NCTA, 256, smem_rnn>>>(time_steps, bias, h0, out);
}